// round 1
// baseline (speedup 1.0000x reference)
#include <cuda_runtime.h>
#include <math.h>

// ---------------- problem constants ----------------
namespace {
constexpr int B_ = 8, L_ = 4800, D_ = 256, H_ = 8, DIM_ = 32;
constexpr int M_ = B_ * L_;            // 38400 rows
constexpr float EPS_ATTN = 1e-6f, EPS_LN = 1e-5f;
constexpr int KV_ELEMS = B_ * H_ * DIM_ * DIM_;   // 65536
constexpr int KS_ELEMS = B_ * H_ * DIM_;          // 2048
}

// ---------------- scratch (static device globals; no allocation) ----------------
__device__ float g_x0[M_ * D_];
__device__ float g_x1[M_ * D_];
__device__ float g_Q [M_ * D_];
__device__ float g_K [M_ * D_];
__device__ float g_V [M_ * D_];
__device__ float g_A [M_ * D_];
__device__ float g_Msg[M_ * D_];
__device__ float g_Hid[M_ * 2 * D_];
__device__ float g_KV[KV_ELEMS];
__device__ float g_Ks[KS_ELEMS];

// ---------------- SGEMM: C[M,N] = act(A[M,K] @ B[K,N] + bias) ----------------
// ACT: 0 = +bias
//      1 = elu(x+bias)+1, then * mask[row]      (Q/K path)
//      2 = (x+bias) * mask[row]                 (V path)
//      3 = relu(x)   (no bias)                  (MLP hidden)
//      4 = x         (no bias)                  (MLP out)
template<int ACT>
__global__ __launch_bounds__(256)
void sgemm_kernel(const float* __restrict__ A, const float* __restrict__ B,
                  const float* __restrict__ bias, const float* __restrict__ mask,
                  float* __restrict__ C, int M, int N, int K)
{
    constexpr int BM = 128, BN = 128, BK = 16;
    __shared__ float As[BK][BM];
    __shared__ float Bs[BK][BN];

    const int tid = threadIdx.x;
    const int tx = tid & 15;          // 0..15 (N direction)
    const int ty = tid >> 4;          // 0..15 (M direction)
    const int rowBase = blockIdx.y * BM;
    const int colBase = blockIdx.x * BN;

    float acc[8][8];
    #pragma unroll
    for (int i = 0; i < 8; i++)
        #pragma unroll
        for (int j = 0; j < 8; j++) acc[i][j] = 0.f;

    for (int k0 = 0; k0 < K; k0 += BK) {
        // load A tile 128x16, store transposed
        #pragma unroll
        for (int it = 0; it < 2; it++) {
            int idx = tid + it * 256;          // 0..511 float4s
            int r = idx >> 2;                  // 0..127
            int c = (idx & 3) * 4;             // 0,4,8,12
            float4 v = *(const float4*)&A[(size_t)(rowBase + r) * K + k0 + c];
            As[c + 0][r] = v.x; As[c + 1][r] = v.y;
            As[c + 2][r] = v.z; As[c + 3][r] = v.w;
        }
        // load B tile 16x128
        #pragma unroll
        for (int it = 0; it < 2; it++) {
            int idx = tid + it * 256;
            int r = idx >> 5;                  // 0..15
            int c = (idx & 31) * 4;            // 0..124
            *(float4*)&Bs[r][c] = *(const float4*)&B[(size_t)(k0 + r) * N + colBase + c];
        }
        __syncthreads();

        #pragma unroll
        for (int k = 0; k < BK; k++) {
            float ra[8], rb[8];
            #pragma unroll
            for (int i = 0; i < 8; i++) ra[i] = As[k][ty * 8 + i];
            #pragma unroll
            for (int j = 0; j < 8; j++) rb[j] = Bs[k][tx * 8 + j];
            #pragma unroll
            for (int i = 0; i < 8; i++)
                #pragma unroll
                for (int j = 0; j < 8; j++)
                    acc[i][j] = fmaf(ra[i], rb[j], acc[i][j]);
        }
        __syncthreads();
    }

    // epilogue
    #pragma unroll
    for (int i = 0; i < 8; i++) {
        int row = rowBase + ty * 8 + i;
        float mk = 1.f;
        if (ACT == 1 || ACT == 2) mk = mask[row];
        #pragma unroll
        for (int j = 0; j < 8; j += 4) {
            int col = colBase + tx * 8 + j;
            float4 v;
            float* vp = &v.x;
            #pragma unroll
            for (int q = 0; q < 4; q++) {
                float t = acc[i][j + q];
                if (ACT == 0 || ACT == 1 || ACT == 2) t += bias[col + q];
                if (ACT == 1) { t = (t > 0.f) ? (t + 1.f) : expf(t); t *= mk; }
                if (ACT == 2) { t *= mk; }
                if (ACT == 3) { t = t > 0.f ? t : 0.f; }
                vp[q] = t;
            }
            *(float4*)&C[(size_t)row * N + col] = v;
        }
    }
}

// ---------------- zero KV / Ksum ----------------
__global__ void zero_kv(float* __restrict__ kv, float* __restrict__ ks)
{
    int i = blockIdx.x * 256 + threadIdx.x;
    if (i < KV_ELEMS) kv[i] = 0.f;
    if (i < KS_ELEMS) ks[i] = 0.f;
}

// ---------------- KV[b,h,m,d] = sum_s K[b,s,h,d] * V[b,s,h,m]; Ksum = sum_s K ----------------
// grid: (B*H, NSPLIT), block 256, atomicAdd reduction across splits
__global__ __launch_bounds__(256)
void kv_kernel(const float* __restrict__ Kp, const float* __restrict__ Vp,
               float* __restrict__ KV, float* __restrict__ Ks, int rowsPerSplit)
{
    const int bh = blockIdx.x;
    const int b = bh >> 3, h = bh & 7;
    const int l0 = blockIdx.y * rowsPerSplit;
    const int tid = threadIdx.x;
    const int lr = tid >> 5;          // 0..7 (row within chunk)
    const int ld = tid & 31;          // 0..31

    __shared__ float Kt[8][32];
    __shared__ float Vt[8][32];

    float a0 = 0.f, a1 = 0.f, a2 = 0.f, a3 = 0.f, ks = 0.f;

    for (int c = 0; c < rowsPerSplit; c += 8) {
        int l = l0 + c + lr;
        size_t base = ((size_t)b * L_ + l) * D_ + h * DIM_ + ld;
        Kt[lr][ld] = Kp[base];
        Vt[lr][ld] = Vp[base];
        __syncthreads();
        #pragma unroll
        for (int r = 0; r < 8; r++) {
            float kv = Kt[r][ld];
            a0 = fmaf(kv, Vt[r][lr +  0], a0);
            a1 = fmaf(kv, Vt[r][lr +  8], a1);
            a2 = fmaf(kv, Vt[r][lr + 16], a2);
            a3 = fmaf(kv, Vt[r][lr + 24], a3);
        }
        if (tid < 32) {
            #pragma unroll
            for (int r = 0; r < 8; r++) ks += Kt[r][tid];
        }
        __syncthreads();
    }

    float* kvb = KV + (size_t)bh * DIM_ * DIM_;
    atomicAdd(&kvb[(lr +  0) * DIM_ + ld], a0);
    atomicAdd(&kvb[(lr +  8) * DIM_ + ld], a1);
    atomicAdd(&kvb[(lr + 16) * DIM_ + ld], a2);
    atomicAdd(&kvb[(lr + 24) * DIM_ + ld], a3);
    if (tid < 32) atomicAdd(&Ks[bh * DIM_ + tid], ks);
}

// ---------------- out[b,l,h,m] = z * sum_d Q[b,l,h,d] * KV[b,h,m,d] ----------------
__global__ __launch_bounds__(256)
void attn_apply(const float* __restrict__ Q, const float* __restrict__ KV,
                const float* __restrict__ Ks, float* __restrict__ Out)
{
    __shared__ float sKV[H_ * DIM_ * DIM_];   // 32 KB
    __shared__ float sKs[H_ * DIM_];          // 1 KB
    const int b = blockIdx.y;
    const int tid = threadIdx.x;

    for (int i = tid; i < H_ * DIM_ * DIM_; i += 256)
        sKV[i] = KV[(size_t)b * H_ * DIM_ * DIM_ + i];
    if (tid < H_ * DIM_) sKs[tid] = Ks[b * H_ * DIM_ + tid];
    __syncthreads();

    const int token = blockIdx.x * 256 + tid;
    if (token >= L_) return;
    const size_t row = (size_t)b * L_ + token;
    const float* q = Q + row * D_;
    float* o = Out + row * D_;

    for (int h = 0; h < H_; h++) {
        float qr[DIM_];
        #pragma unroll
        for (int d = 0; d < DIM_; d++) qr[d] = q[h * DIM_ + d];
        float s = 0.f;
        #pragma unroll
        for (int d = 0; d < DIM_; d++) s = fmaf(qr[d], sKs[h * DIM_ + d], s);
        float z = 1.f / (s + EPS_ATTN);
        const float* kvh = &sKV[h * DIM_ * DIM_];
        #pragma unroll 4
        for (int m = 0; m < DIM_; m++) {
            float acc = 0.f;
            #pragma unroll
            for (int d = 0; d < DIM_; d++) acc = fmaf(kvh[m * DIM_ + d], qr[d], acc);
            o[h * DIM_ + m] = acc * z;
        }
    }
}

// ---------------- layernorm (in place), warp per row ----------------
__global__ __launch_bounds__(256)
void ln_kernel(float* __restrict__ X, const float* __restrict__ g, const float* __restrict__ bta)
{
    const int warp = threadIdx.x >> 5, lane = threadIdx.x & 31;
    const int row = blockIdx.x * 8 + warp;
    const size_t base = (size_t)row * D_ + lane;
    float v[8];
    float s1 = 0.f, s2 = 0.f;
    #pragma unroll
    for (int j = 0; j < 8; j++) {
        v[j] = X[base + j * 32];
        s1 += v[j];
        s2 = fmaf(v[j], v[j], s2);
    }
    #pragma unroll
    for (int o = 16; o; o >>= 1) {
        s1 += __shfl_xor_sync(0xffffffffu, s1, o);
        s2 += __shfl_xor_sync(0xffffffffu, s2, o);
    }
    float mu = s1 * (1.f / D_);
    float var = s2 * (1.f / D_) - mu * mu;
    float rs = rsqrtf(var + EPS_LN);
    #pragma unroll
    for (int j = 0; j < 8; j++) {
        int c = lane + j * 32;
        X[base + j * 32] = (v[j] - mu) * rs * g[c] + bta[c];
    }
}

// ---------------- layernorm of Msg + residual add into X ----------------
__global__ __launch_bounds__(256)
void ln_res_kernel(float* __restrict__ X, const float* __restrict__ Mm,
                   const float* __restrict__ g, const float* __restrict__ bta)
{
    const int warp = threadIdx.x >> 5, lane = threadIdx.x & 31;
    const int row = blockIdx.x * 8 + warp;
    const size_t base = (size_t)row * D_ + lane;
    float v[8];
    float s1 = 0.f, s2 = 0.f;
    #pragma unroll
    for (int j = 0; j < 8; j++) {
        v[j] = Mm[base + j * 32];
        s1 += v[j];
        s2 = fmaf(v[j], v[j], s2);
    }
    #pragma unroll
    for (int o = 16; o; o >>= 1) {
        s1 += __shfl_xor_sync(0xffffffffu, s1, o);
        s2 += __shfl_xor_sync(0xffffffffu, s2, o);
    }
    float mu = s1 * (1.f / D_);
    float var = s2 * (1.f / D_) - mu * mu;
    float rs = rsqrtf(var + EPS_LN);
    #pragma unroll
    for (int j = 0; j < 8; j++) {
        int c = lane + j * 32;
        X[base + j * 32] += (v[j] - mu) * rs * g[c] + bta[c];
    }
}

// ---------------- host orchestration ----------------
namespace {

struct Ptrs {
    float *x0, *x1, *Q, *K, *V, *A, *Msg, *Hid, *KV, *Ks;
};

void run_layer(float* x, const float* src, const float* xm, const float* sm,
               const float* Wq, const float* bq, const float* Wk, const float* bk,
               const float* Wv, const float* bv, const float* Wm, const float* bm,
               const float* w1, const float* w2, const float* g1, const float* b1,
               const float* g2, const float* b2, const Ptrs& p)
{
    dim3 gD(D_ / 128, M_ / 128);         // (2, 300)
    dim3 gH(2 * D_ / 128, M_ / 128);     // (4, 300)

    sgemm_kernel<1><<<gD, 256>>>(x,   Wq, bq, xm, p.Q, M_, D_, D_);
    sgemm_kernel<1><<<gD, 256>>>(src, Wk, bk, sm, p.K, M_, D_, D_);
    sgemm_kernel<2><<<gD, 256>>>(src, Wv, bv, sm, p.V, M_, D_, D_);

    zero_kv<<<(KV_ELEMS + 255) / 256, 256>>>(p.KV, p.Ks);
    kv_kernel<<<dim3(B_ * H_, 20), 256>>>(p.K, p.V, p.KV, p.Ks, L_ / 20);
    attn_apply<<<dim3((L_ + 255) / 256, B_), 256>>>(p.Q, p.KV, p.Ks, p.A);

    sgemm_kernel<0><<<gD, 256>>>(p.A, Wm, bm, nullptr, p.Msg, M_, D_, D_);
    ln_kernel<<<M_ / 8, 256>>>(p.Msg, g1, b1);
    sgemm_kernel<3><<<gH, 256>>>(p.Msg, w1, nullptr, nullptr, p.Hid, M_, 2 * D_, D_);
    sgemm_kernel<4><<<gD, 256>>>(p.Hid, w2, nullptr, nullptr, p.A, M_, D_, 2 * D_);
    ln_res_kernel<<<M_ / 8, 256>>>(x, p.A, g2, b2);
}

} // namespace

extern "C" void kernel_launch(void* const* d_in, const int* in_sizes, int n_in,
                              void* d_out, int out_size)
{
    const float* desc0 = (const float*)d_in[0];
    const float* desc1 = (const float*)d_in[1];
    const float* mask0 = (const float*)d_in[2];
    const float* mask1 = (const float*)d_in[3];
    const float* Wq = (const float*)d_in[4];
    const float* bq = (const float*)d_in[5];
    const float* Wk = (const float*)d_in[6];
    const float* bk = (const float*)d_in[7];
    const float* Wv = (const float*)d_in[8];
    const float* bv = (const float*)d_in[9];
    const float* Wm = (const float*)d_in[10];
    const float* bm = (const float*)d_in[11];
    const float* w1 = (const float*)d_in[12];
    const float* w2 = (const float*)d_in[13];
    const float* g1 = (const float*)d_in[14];
    const float* b1 = (const float*)d_in[15];
    const float* g2 = (const float*)d_in[16];
    const float* b2 = (const float*)d_in[17];

    Ptrs p;
    cudaGetSymbolAddress((void**)&p.x0,  g_x0);
    cudaGetSymbolAddress((void**)&p.x1,  g_x1);
    cudaGetSymbolAddress((void**)&p.Q,   g_Q);
    cudaGetSymbolAddress((void**)&p.K,   g_K);
    cudaGetSymbolAddress((void**)&p.V,   g_V);
    cudaGetSymbolAddress((void**)&p.A,   g_A);
    cudaGetSymbolAddress((void**)&p.Msg, g_Msg);
    cudaGetSymbolAddress((void**)&p.Hid, g_Hid);
    cudaGetSymbolAddress((void**)&p.KV,  g_KV);
    cudaGetSymbolAddress((void**)&p.Ks,  g_Ks);

    const size_t tensorBytes = (size_t)M_ * D_ * sizeof(float);
    cudaMemcpyAsync(p.x0, desc0, tensorBytes, cudaMemcpyDeviceToDevice);
    cudaMemcpyAsync(p.x1, desc1, tensorBytes, cudaMemcpyDeviceToDevice);

    const int w1sz = D_ * 2 * D_;   // per-layer slice of w1
    const int w2sz = 2 * D_ * D_;   // per-layer slice of w2

    for (int li = 0; li < 8; li++) {
        const float* lw1 = w1 + (size_t)li * w1sz;
        const float* lw2 = w2 + (size_t)li * w2sz;
        const float* lg1 = g1 + li * D_;
        const float* lb1 = b1 + li * D_;
        const float* lg2 = g2 + li * D_;
        const float* lb2 = b2 + li * D_;
        if ((li & 1) == 0) {
            // self: both streams attend to their own (pre-update) state
            run_layer(p.x0, p.x0, mask0, mask0, Wq, bq, Wk, bk, Wv, bv, Wm, bm,
                      lw1, lw2, lg1, lb1, lg2, lb2, p);
            run_layer(p.x1, p.x1, mask1, mask1, Wq, bq, Wk, bk, Wv, bv, Wm, bm,
                      lw1, lw2, lg1, lb1, lg2, lb2, p);
        } else {
            // cross: desc0 uses old desc1; desc1 uses UPDATED desc0 (matches reference)
            run_layer(p.x0, p.x1, mask0, mask1, Wq, bq, Wk, bk, Wv, bv, Wm, bm,
                      lw1, lw2, lg1, lb1, lg2, lb2, p);
            run_layer(p.x1, p.x0, mask1, mask0, Wq, bq, Wk, bk, Wv, bv, Wm, bm,
                      lw1, lw2, lg1, lb1, lg2, lb2, p);
        }
    }

    cudaMemcpyAsync((float*)d_out,            p.x0, tensorBytes, cudaMemcpyDeviceToDevice);
    cudaMemcpyAsync((float*)d_out + (size_t)M_ * D_, p.x1, tensorBytes, cudaMemcpyDeviceToDevice);
}

// round 2
// speedup vs baseline: 1.7213x; 1.7213x over previous
#include <cuda_runtime.h>
#include <math.h>
#include <stdint.h>

// ---------------- problem constants ----------------
namespace {
constexpr int B_ = 8, L_ = 4800, D_ = 256, H_ = 8, DIM_ = 32;
constexpr int M_ = B_ * L_;            // 38400 rows
constexpr float EPS_ATTN = 1e-6f, EPS_LN = 1e-5f;
constexpr int KV_ELEMS = B_ * H_ * DIM_ * DIM_;   // 65536
constexpr int KS_ELEMS = B_ * H_ * DIM_;          // 2048
}

// ---------------- scratch (static device globals; no allocation) ----------------
__device__ float g_x0[M_ * D_];
__device__ float g_x1[M_ * D_];
__device__ float g_Q [M_ * D_];
__device__ float g_K [M_ * D_];
__device__ float g_V [M_ * D_];
__device__ float g_A [M_ * D_];
__device__ float g_Msg[M_ * D_];
__device__ float g_Hid[M_ * 2 * D_];
__device__ float g_KV[KV_ELEMS];
__device__ float g_Ks[KS_ELEMS];

// ---------------- helpers ----------------
__device__ __forceinline__ uint32_t f2tf32(float f) {
    uint32_t u;
    asm("cvt.rna.tf32.f32 %0, %1;" : "=r"(u) : "f"(f));
    return u;
}

__device__ __forceinline__ void mma_tf32(float d[4], const uint32_t a[4], const uint32_t b[2]) {
    asm volatile(
        "mma.sync.aligned.m16n8k8.row.col.f32.tf32.tf32.f32 "
        "{%0,%1,%2,%3}, {%4,%5,%6,%7}, {%8,%9}, {%0,%1,%2,%3};\n"
        : "+f"(d[0]), "+f"(d[1]), "+f"(d[2]), "+f"(d[3])
        : "r"(a[0]), "r"(a[1]), "r"(a[2]), "r"(a[3]), "r"(b[0]), "r"(b[1]));
}

// ---------------- TF32 tensor-core GEMM: C[M,N] = act(A[M,K] @ B[K,N] + bias) ----------------
// ACT: 0 = +bias
//      1 = elu(x+bias)+1, then * mask[row]      (Q/K path)
//      2 = (x+bias) * mask[row]                 (V path)
//      3 = relu(x)   (no bias)                  (MLP hidden)
//      4 = x         (no bias)                  (MLP out)
template<int ACT>
__global__ __launch_bounds__(256, 2)
void gemm_tc(const float* __restrict__ A, const float* __restrict__ Bm,
             const float* __restrict__ bias, const float* __restrict__ mask,
             float* __restrict__ C, int M, int N, int K)
{
    constexpr int BM = 128, BN = 128, BK = 32;
    constexpr int LDSA = BM + 8;     // 136 -> 136%32==8, conflict-free frag loads
    __shared__ uint32_t As[BK][LDSA];   // [k][m] (transposed)
    __shared__ uint32_t Bs[BK][LDSA];   // [k][n]

    const int tid  = threadIdx.x;
    const int warp = tid >> 5, lane = tid & 31;
    const int wm = warp >> 2, wn = warp & 3;      // 2 x 4 warp grid
    const int rowBase = blockIdx.y * BM;
    const int colBase = blockIdx.x * BN;
    const int wmBase = wm * 64, wnBase = wn * 32; // warp tile 64 x 32
    const int gid = lane >> 2, qid = lane & 3;

    float acc[4][4][4];
    #pragma unroll
    for (int i = 0; i < 4; i++)
        #pragma unroll
        for (int j = 0; j < 4; j++)
            #pragma unroll
            for (int q = 0; q < 4; q++) acc[i][j][q] = 0.f;

    for (int k0 = 0; k0 < K; k0 += BK) {
        // ---- stage A tile (128 x 32), store transposed as tf32 ----
        #pragma unroll
        for (int it = 0; it < 4; it++) {
            int idx = tid + it * 256;            // 0..1023 float4 slots
            int r   = idx & 127;                 // row within tile
            int c4  = idx >> 7;                  // 0..7 (k/4)
            float4 v = *(const float4*)&A[(size_t)(rowBase + r) * K + k0 + c4 * 4];
            As[c4 * 4 + 0][r] = f2tf32(v.x);
            As[c4 * 4 + 1][r] = f2tf32(v.y);
            As[c4 * 4 + 2][r] = f2tf32(v.z);
            As[c4 * 4 + 3][r] = f2tf32(v.w);
        }
        // ---- stage B tile (32 x 128) as tf32 ----
        #pragma unroll
        for (int it = 0; it < 4; it++) {
            int idx = tid + it * 256;
            int c4  = idx & 31;                  // col/4
            int r   = idx >> 5;                  // 0..31 (k)
            float4 v = *(const float4*)&Bm[(size_t)(k0 + r) * N + colBase + c4 * 4];
            uint32_t* dst = &Bs[r][c4 * 4];
            dst[0] = f2tf32(v.x); dst[1] = f2tf32(v.y);
            dst[2] = f2tf32(v.z); dst[3] = f2tf32(v.w);
        }
        __syncthreads();

        #pragma unroll
        for (int ks = 0; ks < 4; ks++) {
            const int kb = ks * 8;
            uint32_t af[4][4], bf[4][2];
            #pragma unroll
            for (int i = 0; i < 4; i++) {
                int m0 = wmBase + i * 16;
                af[i][0] = As[kb + qid    ][m0 + gid    ];
                af[i][1] = As[kb + qid    ][m0 + gid + 8];
                af[i][2] = As[kb + qid + 4][m0 + gid    ];
                af[i][3] = As[kb + qid + 4][m0 + gid + 8];
            }
            #pragma unroll
            for (int j = 0; j < 4; j++) {
                int n0 = wnBase + j * 8;
                bf[j][0] = Bs[kb + qid    ][n0 + gid];
                bf[j][1] = Bs[kb + qid + 4][n0 + gid];
            }
            #pragma unroll
            for (int i = 0; i < 4; i++)
                #pragma unroll
                for (int j = 0; j < 4; j++)
                    mma_tf32(acc[i][j], af[i], bf[j]);
        }
        __syncthreads();
    }

    // ---- epilogue ----
    #pragma unroll
    for (int i = 0; i < 4; i++) {
        int r0 = rowBase + wmBase + i * 16 + gid;
        int r1 = r0 + 8;
        float mk0 = 1.f, mk1 = 1.f;
        if (ACT == 1 || ACT == 2) { mk0 = mask[r0]; mk1 = mask[r1]; }
        #pragma unroll
        for (int j = 0; j < 4; j++) {
            int col = colBase + wnBase + j * 8 + qid * 2;
            float b0 = 0.f, b1 = 0.f;
            if (ACT == 0 || ACT == 1 || ACT == 2) { b0 = bias[col]; b1 = bias[col + 1]; }
            float v[4];
            v[0] = acc[i][j][0] + b0;  v[1] = acc[i][j][1] + b1;
            v[2] = acc[i][j][2] + b0;  v[3] = acc[i][j][3] + b1;
            if (ACT == 1) {
                #pragma unroll
                for (int q = 0; q < 4; q++) v[q] = (v[q] > 0.f) ? (v[q] + 1.f) : expf(v[q]);
                v[0] *= mk0; v[1] *= mk0; v[2] *= mk1; v[3] *= mk1;
            }
            if (ACT == 2) { v[0] *= mk0; v[1] *= mk0; v[2] *= mk1; v[3] *= mk1; }
            if (ACT == 3) {
                #pragma unroll
                for (int q = 0; q < 4; q++) v[q] = v[q] > 0.f ? v[q] : 0.f;
            }
            *(float2*)&C[(size_t)r0 * N + col] = make_float2(v[0], v[1]);
            *(float2*)&C[(size_t)r1 * N + col] = make_float2(v[2], v[3]);
        }
    }
}

// ---------------- zero KV / Ksum ----------------
__global__ void zero_kv(float* __restrict__ kv, float* __restrict__ ks)
{
    int i = blockIdx.x * 256 + threadIdx.x;
    if (i < KV_ELEMS) kv[i] = 0.f;
    if (i < KS_ELEMS) ks[i] = 0.f;
}

// ---------------- KV[b,h,m,d] = sum_s K[b,s,h,d] * V[b,s,h,m]; Ksum = sum_s K ----------------
__global__ __launch_bounds__(256)
void kv_kernel(const float* __restrict__ Kp, const float* __restrict__ Vp,
               float* __restrict__ KV, float* __restrict__ Ks, int rowsPerSplit)
{
    const int bh = blockIdx.x;
    const int b = bh >> 3, h = bh & 7;
    const int l0 = blockIdx.y * rowsPerSplit;
    const int tid = threadIdx.x;
    const int lr = tid >> 5;          // 0..7 (row within chunk)
    const int ld = tid & 31;          // 0..31

    __shared__ float Kt[8][32];
    __shared__ float Vt[8][32];

    float a0 = 0.f, a1 = 0.f, a2 = 0.f, a3 = 0.f, ks = 0.f;

    for (int c = 0; c < rowsPerSplit; c += 8) {
        int l = l0 + c + lr;
        size_t base = ((size_t)b * L_ + l) * D_ + h * DIM_ + ld;
        Kt[lr][ld] = Kp[base];
        Vt[lr][ld] = Vp[base];
        __syncthreads();
        #pragma unroll
        for (int r = 0; r < 8; r++) {
            float kv = Kt[r][ld];
            a0 = fmaf(kv, Vt[r][lr +  0], a0);
            a1 = fmaf(kv, Vt[r][lr +  8], a1);
            a2 = fmaf(kv, Vt[r][lr + 16], a2);
            a3 = fmaf(kv, Vt[r][lr + 24], a3);
        }
        if (tid < 32) {
            #pragma unroll
            for (int r = 0; r < 8; r++) ks += Kt[r][tid];
        }
        __syncthreads();
    }

    float* kvb = KV + (size_t)bh * DIM_ * DIM_;
    atomicAdd(&kvb[(lr +  0) * DIM_ + ld], a0);
    atomicAdd(&kvb[(lr +  8) * DIM_ + ld], a1);
    atomicAdd(&kvb[(lr + 16) * DIM_ + ld], a2);
    atomicAdd(&kvb[(lr + 24) * DIM_ + ld], a3);
    if (tid < 32) atomicAdd(&Ks[bh * DIM_ + tid], ks);
}

// ---------------- out[b,l,h,m] = z * sum_d Q[b,l,h,d] * KV[b,h,m,d] ----------------
__global__ __launch_bounds__(256)
void attn_apply(const float* __restrict__ Q, const float* __restrict__ KV,
                const float* __restrict__ Ks, float* __restrict__ Out)
{
    __shared__ float sKV[H_ * DIM_ * DIM_];   // 32 KB
    __shared__ float sKs[H_ * DIM_];          // 1 KB
    const int b = blockIdx.y;
    const int tid = threadIdx.x;

    for (int i = tid; i < H_ * DIM_ * DIM_; i += 256)
        sKV[i] = KV[(size_t)b * H_ * DIM_ * DIM_ + i];
    if (tid < H_ * DIM_) sKs[tid] = Ks[b * H_ * DIM_ + tid];
    __syncthreads();

    const int token = blockIdx.x * 256 + tid;
    if (token >= L_) return;
    const size_t row = (size_t)b * L_ + token;
    const float* q = Q + row * D_;
    float* o = Out + row * D_;

    for (int h = 0; h < H_; h++) {
        float qr[DIM_];
        #pragma unroll
        for (int d = 0; d < DIM_; d++) qr[d] = q[h * DIM_ + d];
        float s = 0.f;
        #pragma unroll
        for (int d = 0; d < DIM_; d++) s = fmaf(qr[d], sKs[h * DIM_ + d], s);
        float z = 1.f / (s + EPS_ATTN);
        const float* kvh = &sKV[h * DIM_ * DIM_];
        #pragma unroll 4
        for (int m = 0; m < DIM_; m++) {
            float acc = 0.f;
            #pragma unroll
            for (int d = 0; d < DIM_; d++) acc = fmaf(kvh[m * DIM_ + d], qr[d], acc);
            o[h * DIM_ + m] = acc * z;
        }
    }
}

// ---------------- layernorm (in place), warp per row ----------------
__global__ __launch_bounds__(256)
void ln_kernel(float* __restrict__ X, const float* __restrict__ g, const float* __restrict__ bta)
{
    const int warp = threadIdx.x >> 5, lane = threadIdx.x & 31;
    const int row = blockIdx.x * 8 + warp;
    const size_t base = (size_t)row * D_ + lane;
    float v[8];
    float s1 = 0.f, s2 = 0.f;
    #pragma unroll
    for (int j = 0; j < 8; j++) {
        v[j] = X[base + j * 32];
        s1 += v[j];
        s2 = fmaf(v[j], v[j], s2);
    }
    #pragma unroll
    for (int o = 16; o; o >>= 1) {
        s1 += __shfl_xor_sync(0xffffffffu, s1, o);
        s2 += __shfl_xor_sync(0xffffffffu, s2, o);
    }
    float mu = s1 * (1.f / D_);
    float var = s2 * (1.f / D_) - mu * mu;
    float rs = rsqrtf(var + EPS_LN);
    #pragma unroll
    for (int j = 0; j < 8; j++) {
        int c = lane + j * 32;
        X[base + j * 32] = (v[j] - mu) * rs * g[c] + bta[c];
    }
}

// ---------------- layernorm of Msg + residual add into X ----------------
__global__ __launch_bounds__(256)
void ln_res_kernel(float* __restrict__ X, const float* __restrict__ Mm,
                   const float* __restrict__ g, const float* __restrict__ bta)
{
    const int warp = threadIdx.x >> 5, lane = threadIdx.x & 31;
    const int row = blockIdx.x * 8 + warp;
    const size_t base = (size_t)row * D_ + lane;
    float v[8];
    float s1 = 0.f, s2 = 0.f;
    #pragma unroll
    for (int j = 0; j < 8; j++) {
        v[j] = Mm[base + j * 32];
        s1 += v[j];
        s2 = fmaf(v[j], v[j], s2);
    }
    #pragma unroll
    for (int o = 16; o; o >>= 1) {
        s1 += __shfl_xor_sync(0xffffffffu, s1, o);
        s2 += __shfl_xor_sync(0xffffffffu, s2, o);
    }
    float mu = s1 * (1.f / D_);
    float var = s2 * (1.f / D_) - mu * mu;
    float rs = rsqrtf(var + EPS_LN);
    #pragma unroll
    for (int j = 0; j < 8; j++) {
        int c = lane + j * 32;
        X[base + j * 32] += (v[j] - mu) * rs * g[c] + bta[c];
    }
}

// ---------------- host orchestration ----------------
namespace {

struct Ptrs {
    float *x0, *x1, *Q, *K, *V, *A, *Msg, *Hid, *KV, *Ks;
};

void run_layer(float* x, const float* src, const float* xm, const float* sm,
               const float* Wq, const float* bq, const float* Wk, const float* bk,
               const float* Wv, const float* bv, const float* Wm, const float* bm,
               const float* w1, const float* w2, const float* g1, const float* b1,
               const float* g2, const float* b2, const Ptrs& p)
{
    dim3 gD(D_ / 128, M_ / 128);         // (2, 300)
    dim3 gH(2 * D_ / 128, M_ / 128);     // (4, 300)

    gemm_tc<1><<<gD, 256>>>(x,   Wq, bq, xm, p.Q, M_, D_, D_);
    gemm_tc<1><<<gD, 256>>>(src, Wk, bk, sm, p.K, M_, D_, D_);
    gemm_tc<2><<<gD, 256>>>(src, Wv, bv, sm, p.V, M_, D_, D_);

    zero_kv<<<(KV_ELEMS + 255) / 256, 256>>>(p.KV, p.Ks);
    kv_kernel<<<dim3(B_ * H_, 20), 256>>>(p.K, p.V, p.KV, p.Ks, L_ / 20);
    attn_apply<<<dim3((L_ + 255) / 256, B_), 256>>>(p.Q, p.KV, p.Ks, p.A);

    gemm_tc<0><<<gD, 256>>>(p.A, Wm, bm, nullptr, p.Msg, M_, D_, D_);
    ln_kernel<<<M_ / 8, 256>>>(p.Msg, g1, b1);
    gemm_tc<3><<<gH, 256>>>(p.Msg, w1, nullptr, nullptr, p.Hid, M_, 2 * D_, D_);
    gemm_tc<4><<<gD, 256>>>(p.Hid, w2, nullptr, nullptr, p.A, M_, D_, 2 * D_);
    ln_res_kernel<<<M_ / 8, 256>>>(x, p.A, g2, b2);
}

} // namespace

extern "C" void kernel_launch(void* const* d_in, const int* in_sizes, int n_in,
                              void* d_out, int out_size)
{
    const float* desc0 = (const float*)d_in[0];
    const float* desc1 = (const float*)d_in[1];
    const float* mask0 = (const float*)d_in[2];
    const float* mask1 = (const float*)d_in[3];
    const float* Wq = (const float*)d_in[4];
    const float* bq = (const float*)d_in[5];
    const float* Wk = (const float*)d_in[6];
    const float* bk = (const float*)d_in[7];
    const float* Wv = (const float*)d_in[8];
    const float* bv = (const float*)d_in[9];
    const float* Wm = (const float*)d_in[10];
    const float* bm = (const float*)d_in[11];
    const float* w1 = (const float*)d_in[12];
    const float* w2 = (const float*)d_in[13];
    const float* g1 = (const float*)d_in[14];
    const float* b1 = (const float*)d_in[15];
    const float* g2 = (const float*)d_in[16];
    const float* b2 = (const float*)d_in[17];

    Ptrs p;
    cudaGetSymbolAddress((void**)&p.x0,  g_x0);
    cudaGetSymbolAddress((void**)&p.x1,  g_x1);
    cudaGetSymbolAddress((void**)&p.Q,   g_Q);
    cudaGetSymbolAddress((void**)&p.K,   g_K);
    cudaGetSymbolAddress((void**)&p.V,   g_V);
    cudaGetSymbolAddress((void**)&p.A,   g_A);
    cudaGetSymbolAddress((void**)&p.Msg, g_Msg);
    cudaGetSymbolAddress((void**)&p.Hid, g_Hid);
    cudaGetSymbolAddress((void**)&p.KV,  g_KV);
    cudaGetSymbolAddress((void**)&p.Ks,  g_Ks);

    const size_t tensorBytes = (size_t)M_ * D_ * sizeof(float);
    cudaMemcpyAsync(p.x0, desc0, tensorBytes, cudaMemcpyDeviceToDevice);
    cudaMemcpyAsync(p.x1, desc1, tensorBytes, cudaMemcpyDeviceToDevice);

    const int w1sz = D_ * 2 * D_;   // per-layer slice of w1
    const int w2sz = 2 * D_ * D_;   // per-layer slice of w2

    for (int li = 0; li < 8; li++) {
        const float* lw1 = w1 + (size_t)li * w1sz;
        const float* lw2 = w2 + (size_t)li * w2sz;
        const float* lg1 = g1 + li * D_;
        const float* lb1 = b1 + li * D_;
        const float* lg2 = g2 + li * D_;
        const float* lb2 = b2 + li * D_;
        if ((li & 1) == 0) {
            run_layer(p.x0, p.x0, mask0, mask0, Wq, bq, Wk, bk, Wv, bv, Wm, bm,
                      lw1, lw2, lg1, lb1, lg2, lb2, p);
            run_layer(p.x1, p.x1, mask1, mask1, Wq, bq, Wk, bk, Wv, bv, Wm, bm,
                      lw1, lw2, lg1, lb1, lg2, lb2, p);
        } else {
            run_layer(p.x0, p.x1, mask0, mask1, Wq, bq, Wk, bk, Wv, bv, Wm, bm,
                      lw1, lw2, lg1, lb1, lg2, lb2, p);
            run_layer(p.x1, p.x0, mask1, mask0, Wq, bq, Wk, bk, Wv, bv, Wm, bm,
                      lw1, lw2, lg1, lb1, lg2, lb2, p);
        }
    }

    cudaMemcpyAsync((float*)d_out,            p.x0, tensorBytes, cudaMemcpyDeviceToDevice);
    cudaMemcpyAsync((float*)d_out + (size_t)M_ * D_, p.x1, tensorBytes, cudaMemcpyDeviceToDevice);
}

// round 4
// speedup vs baseline: 1.9011x; 1.1045x over previous
#include <cuda_runtime.h>
#include <math.h>
#include <stdint.h>

// ================= problem constants =================
namespace {
constexpr int B_ = 8, L_ = 4800, D_ = 256, H_ = 8, DIM_ = 32;
constexpr int M_ = B_ * L_;            // 38400 rows
constexpr float EPS_ATTN = 1e-6f, EPS_LN = 1e-5f;
constexpr int KV_ELEMS = B_ * H_ * DIM_ * DIM_;   // 65536
constexpr int KS_ELEMS = B_ * H_ * DIM_;          // 2048

// GEMM tile config: CTA 64x256, BK=32, 8 warps (2 x 4), warp tile 32x64
constexpr int BM = 64, BN = 256, BK = 32;
constexpr int LDA = 72;                // As row stride (floats): (qid*72+gid)%32 distinct
constexpr int LDB = 36;                // Bs row stride (floats): (gid*36+qid)%32 distinct
constexpr int AS_STG = BK * LDA;       // 2304 floats per stage
constexpr int BS_STG = BN * LDB;       // 9216 floats per stage
constexpr int AS_OFF = 0;
constexpr int BS_OFF = 2 * AS_STG;             // 4608
constexpr int PRM_OFF = BS_OFF + 2 * BS_STG;   // 23040
constexpr int SMEM_FLOATS = PRM_OFF + 768;     // sbias 256, sg 256, sb 256
constexpr int SMEM_BYTES = SMEM_FLOATS * 4;    // 95232 bytes
}

// ================= scratch (static device globals) =================
__device__ float g_x0[M_ * D_];
__device__ float g_x1[M_ * D_];
__device__ float g_Q [M_ * D_];
__device__ float g_K [M_ * D_];
__device__ float g_V [M_ * D_];
__device__ float g_A [M_ * D_];
__device__ float g_Msg[M_ * D_];
__device__ float g_Hid[M_ * 2 * D_];
__device__ float g_KV[KV_ELEMS];
__device__ float g_Ks[KS_ELEMS];
__device__ float g_WT [4 * D_ * D_];          // WqT,WkT,WvT,WmT  [N,K] tf32-rounded
__device__ float g_w1T[8 * 2 * D_ * D_];      // [512,256] per layer
__device__ float g_w2T[8 * D_ * 2 * D_];      // [256,512] per layer

// ================= helpers =================
__device__ __forceinline__ uint32_t f2tf32(float f) {
    uint32_t u;
    asm("cvt.rna.tf32.f32 %0, %1;" : "=r"(u) : "f"(f));
    return u;
}

__device__ __forceinline__ void mma_tf32(float d[4], const uint32_t a[4], const uint32_t b[2]) {
    asm volatile(
        "mma.sync.aligned.m16n8k8.row.col.f32.tf32.tf32.f32 "
        "{%0,%1,%2,%3}, {%4,%5,%6,%7}, {%8,%9}, {%0,%1,%2,%3};\n"
        : "+f"(d[0]), "+f"(d[1]), "+f"(d[2]), "+f"(d[3])
        : "r"(a[0]), "r"(a[1]), "r"(a[2]), "r"(a[3]), "r"(b[0]), "r"(b[1]));
}

// ================= pipelined TF32 mma GEMM =================
// C[M,N] = epi(A[M,K] @ BT[N,K]^T); BT pre-rounded to tf32 bit patterns.
enum { EPI_QK = 1, EPI_V = 2, EPI_RELU = 3, EPI_BIAS_LN = 5, EPI_LN_RES = 6 };

template<int EPI>
__global__ __launch_bounds__(256, 2)
void gemm_mma(const float* __restrict__ A, const float* __restrict__ BT,
              const float* __restrict__ bias, const float* __restrict__ mask,
              const float* __restrict__ lng, const float* __restrict__ lnb,
              float* __restrict__ C, int N, int K)
{
    extern __shared__ float sm[];
    float* As    = sm + AS_OFF;            // [2][32][LDA] transposed (k-major)
    float* Bs    = sm + BS_OFF;            // [2][256][LDB] n-major
    float* sbias = sm + PRM_OFF;
    float* sg    = sbias + 256;
    float* sb    = sg + 256;
    // epilogue reduction scratch (reuses As region after mainloop)
    float* red1 = As;            // [64][4]
    float* red2 = As + 256;      // [64][4]
    float* smu  = As + 512;      // [64]
    float* srs  = As + 576;      // [64]

    const int tid = threadIdx.x;
    const int warp = tid >> 5, lane = tid & 31;
    const int wm = warp >> 2, wn = warp & 3;       // 2 x 4 warps
    const int gid = lane >> 2, qid = lane & 3;
    const int rowBase = blockIdx.y * BM;
    const int colBase = blockIdx.x * BN;
    const int NK = K / BK;

    if (EPI == EPI_QK || EPI == EPI_V || EPI == EPI_BIAS_LN) {
        if (tid < 256) sbias[tid] = bias[colBase + tid];
    }
    if (EPI == EPI_BIAS_LN || EPI == EPI_LN_RES) {
        if (tid < 256) { sg[tid] = lng[tid]; sb[tid] = lnb[tid]; }
    }

    const uint32_t sm_u32 = (uint32_t)__cvta_generic_to_shared(sm);

    // A staging: thread handles row = tid&63, k-segment (tid>>6)*8 .. +8
    const int arow = tid & 63, aseg = tid >> 6;
    const float* Aptr = A + (size_t)(rowBase + arow) * K + aseg * 8;
    float4 abuf[2][2];

    #define LDG_A(c, bi)                                                         \
        do { abuf[bi][0] = *(const float4*)(Aptr + (size_t)(c) * 32);            \
             abuf[bi][1] = *(const float4*)(Aptr + (size_t)(c) * 32 + 4);        \
        } while (0)

    #define STS_A(s, bi)                                                         \
        do { float* _dst = As + (s) * AS_STG;                                    \
            const float* _f = (const float*)abuf[bi];                            \
            _Pragma("unroll")                                                    \
            for (int _i = 0; _i < 8; _i++)                                       \
                _dst[(aseg * 8 + _i) * LDA + arow] = __uint_as_float(f2tf32(_f[_i])); \
        } while (0)

    #define LDG_B(c, s)                                                          \
        do { uint32_t _sb = sm_u32 + (BS_OFF + (s) * BS_STG) * 4;                \
            const float* _Bsrc = BT + (size_t)colBase * K + (size_t)(c) * 32;    \
            _Pragma("unroll")                                                    \
            for (int _it = 0; _it < 8; _it++) {                                  \
                int _j = tid + _it * 256;                                        \
                int _n = _j >> 3, _kq = (_j & 7) * 4;                            \
                const float* _src = _Bsrc + (size_t)_n * K + _kq;                \
                asm volatile("cp.async.cg.shared.global [%0], [%1], 16;"         \
                             :: "r"(_sb + (uint32_t)(_n * LDB + _kq) * 4), "l"(_src)); \
            }                                                                     \
            asm volatile("cp.async.commit_group;");                              \
        } while (0)

    float acc[2][8][4];
    #pragma unroll
    for (int mi = 0; mi < 2; mi++)
        #pragma unroll
        for (int j = 0; j < 8; j++)
            #pragma unroll
            for (int q = 0; q < 4; q++) acc[mi][j][q] = 0.f;

    // prologue
    LDG_A(0, 0);
    STS_A(0, 0);
    LDG_B(0, 0);

    for (int k = 0; k < NK; k++) {
        const int s = k & 1;
        if (k + 1 < NK) LDG_A(k + 1, (k + 1) & 1);
        asm volatile("cp.async.wait_group 0;" ::: "memory");
        __syncthreads();
        if (k + 1 < NK) { STS_A(s ^ 1, (k + 1) & 1); LDG_B(k + 1, s ^ 1); }

        const float* as = As + s * AS_STG;
        const float* bs = Bs + s * BS_STG;
        #pragma unroll
        for (int ks = 0; ks < 4; ks++) {
            const int kb = ks * 8;
            uint32_t af[2][4], bf[8][2];
            #pragma unroll
            for (int mi = 0; mi < 2; mi++) {
                const float* a_ = as + (kb + qid) * LDA + wm * 32 + mi * 16 + gid;
                af[mi][0] = __float_as_uint(a_[0]);
                af[mi][1] = __float_as_uint(a_[8]);
                af[mi][2] = __float_as_uint(a_[4 * LDA]);
                af[mi][3] = __float_as_uint(a_[4 * LDA + 8]);
            }
            #pragma unroll
            for (int j = 0; j < 8; j++) {
                const float* b_ = bs + (wn * 64 + j * 8 + gid) * LDB + kb + qid;
                bf[j][0] = __float_as_uint(b_[0]);
                bf[j][1] = __float_as_uint(b_[4]);
            }
            #pragma unroll
            for (int mi = 0; mi < 2; mi++)
                #pragma unroll
                for (int j = 0; j < 8; j++)
                    mma_tf32(acc[mi][j], af[mi], bf[j]);
        }
    }
    __syncthreads();   // mainloop done; safe to reuse As for reductions

    // ================= epilogue =================
    // element (mi,j,q): row_loc = wm*32 + mi*16 + (q>>1)*8 + gid
    //                   col_loc = wn*64 + j*8 + qid*2 + (q&1)
    // bias + activation
    if (EPI == EPI_QK || EPI == EPI_V || EPI == EPI_BIAS_LN) {
        #pragma unroll
        for (int mi = 0; mi < 2; mi++)
            #pragma unroll
            for (int j = 0; j < 8; j++) {
                const int c = wn * 64 + j * 8 + qid * 2;
                acc[mi][j][0] += sbias[c];     acc[mi][j][1] += sbias[c + 1];
                acc[mi][j][2] += sbias[c];     acc[mi][j][3] += sbias[c + 1];
            }
    }
    if (EPI == EPI_QK || EPI == EPI_V) {
        float mk[2][2];
        #pragma unroll
        for (int mi = 0; mi < 2; mi++)
            #pragma unroll
            for (int r = 0; r < 2; r++)
                mk[mi][r] = mask[rowBase + wm * 32 + mi * 16 + r * 8 + gid];
        #pragma unroll
        for (int mi = 0; mi < 2; mi++)
            #pragma unroll
            for (int j = 0; j < 8; j++)
                #pragma unroll
                for (int q = 0; q < 4; q++) {
                    float t = acc[mi][j][q];
                    if (EPI == EPI_QK) t = (t > 0.f) ? (t + 1.f) : expf(t);
                    acc[mi][j][q] = t * mk[mi][q >> 1];
                }
    }
    if (EPI == EPI_RELU) {
        #pragma unroll
        for (int mi = 0; mi < 2; mi++)
            #pragma unroll
            for (int j = 0; j < 8; j++)
                #pragma unroll
                for (int q = 0; q < 4; q++)
                    acc[mi][j][q] = acc[mi][j][q] > 0.f ? acc[mi][j][q] : 0.f;
    }

    if (EPI == EPI_BIAS_LN || EPI == EPI_LN_RES) {
        // per-row stats over 256 cols: thread partial -> quad shfl -> cross-warp smem
        float s1[2][2] = {{0.f, 0.f}, {0.f, 0.f}};
        float s2[2][2] = {{0.f, 0.f}, {0.f, 0.f}};
        #pragma unroll
        for (int mi = 0; mi < 2; mi++)
            #pragma unroll
            for (int j = 0; j < 8; j++)
                #pragma unroll
                for (int q = 0; q < 4; q++) {
                    float v = acc[mi][j][q];
                    s1[mi][q >> 1] += v;
                    s2[mi][q >> 1] = fmaf(v, v, s2[mi][q >> 1]);
                }
        #pragma unroll
        for (int o = 1; o <= 2; o <<= 1)
            #pragma unroll
            for (int mi = 0; mi < 2; mi++)
                #pragma unroll
                for (int r = 0; r < 2; r++) {
                    s1[mi][r] += __shfl_xor_sync(0xffffffffu, s1[mi][r], o);
                    s2[mi][r] += __shfl_xor_sync(0xffffffffu, s2[mi][r], o);
                }
        if (qid == 0) {
            #pragma unroll
            for (int mi = 0; mi < 2; mi++)
                #pragma unroll
                for (int r = 0; r < 2; r++) {
                    int rl = wm * 32 + mi * 16 + r * 8 + gid;
                    red1[rl * 4 + wn] = s1[mi][r];
                    red2[rl * 4 + wn] = s2[mi][r];
                }
        }
        __syncthreads();
        if (tid < 64) {
            float a  = red1[tid * 4] + red1[tid * 4 + 1] + red1[tid * 4 + 2] + red1[tid * 4 + 3];
            float b2 = red2[tid * 4] + red2[tid * 4 + 1] + red2[tid * 4 + 2] + red2[tid * 4 + 3];
            float mu = a * (1.f / 256.f);
            float var = b2 * (1.f / 256.f) - mu * mu;
            smu[tid] = mu;
            srs[tid] = rsqrtf(var + EPS_LN);
        }
        __syncthreads();
        #pragma unroll
        for (int mi = 0; mi < 2; mi++)
            #pragma unroll
            for (int j = 0; j < 8; j++)
                #pragma unroll
                for (int q = 0; q < 4; q++) {
                    int rl = wm * 32 + mi * 16 + (q >> 1) * 8 + gid;
                    int c  = wn * 64 + j * 8 + qid * 2 + (q & 1);
                    acc[mi][j][q] = (acc[mi][j][q] - smu[rl]) * srs[rl] * sg[c] + sb[c];
                }
    }

    // store (float2 per row pair)
    #pragma unroll
    for (int mi = 0; mi < 2; mi++) {
        #pragma unroll
        for (int j = 0; j < 8; j++) {
            const int c  = colBase + wn * 64 + j * 8 + qid * 2;
            const int r0 = rowBase + wm * 32 + mi * 16 + gid;
            const int r1 = r0 + 8;
            float2 v0 = make_float2(acc[mi][j][0], acc[mi][j][1]);
            float2 v1 = make_float2(acc[mi][j][2], acc[mi][j][3]);
            if (EPI == EPI_LN_RES) {
                float2 x0 = *(const float2*)&C[(size_t)r0 * N + c];
                float2 x1 = *(const float2*)&C[(size_t)r1 * N + c];
                v0.x += x0.x; v0.y += x0.y;
                v1.x += x1.x; v1.y += x1.y;
            }
            *(float2*)&C[(size_t)r0 * N + c] = v0;
            *(float2*)&C[(size_t)r1 * N + c] = v1;
        }
    }
    #undef LDG_A
    #undef STS_A
    #undef LDG_B
}

// ================= weight transpose + tf32 rounding =================
// in [K,N] -> out [N,K] (rounded rna to tf32)
__global__ void transpose_round(const float* __restrict__ in, float* __restrict__ out,
                                int K, int N)
{
    __shared__ float t[32][33];
    in  += (size_t)blockIdx.z * K * N;
    out += (size_t)blockIdx.z * K * N;
    const int n0 = blockIdx.x * 32, k0 = blockIdx.y * 32;
    const int x = threadIdx.x, y = threadIdx.y;
    #pragma unroll
    for (int i = 0; i < 32; i += 8)
        t[y + i][x] = in[(size_t)(k0 + y + i) * N + n0 + x];
    __syncthreads();
    #pragma unroll
    for (int i = 0; i < 32; i += 8)
        out[(size_t)(n0 + y + i) * K + k0 + x] = __uint_as_float(f2tf32(t[x][y + i]));
}

// ================= zero KV / Ksum =================
__global__ void zero_kv(float* __restrict__ kv, float* __restrict__ ks)
{
    int i = blockIdx.x * 256 + threadIdx.x;
    if (i < KV_ELEMS) kv[i] = 0.f;
    if (i < KS_ELEMS) ks[i] = 0.f;
}

// ================= KV[b,h,m,d] = sum_s K[b,s,h,d]*V[b,s,h,m]; Ksum = sum_s K =================
__global__ __launch_bounds__(256)
void kv_kernel(const float* __restrict__ Kp, const float* __restrict__ Vp,
               float* __restrict__ KV, float* __restrict__ Ks, int rowsPerSplit)
{
    const int bh = blockIdx.x;
    const int b = bh >> 3, h = bh & 7;
    const int l0 = blockIdx.y * rowsPerSplit;
    const int tid = threadIdx.x;
    const int lr = tid >> 5;
    const int ld = tid & 31;

    __shared__ float Kt[8][32];
    __shared__ float Vt[8][32];

    float a0 = 0.f, a1 = 0.f, a2 = 0.f, a3 = 0.f, ks = 0.f;

    for (int c = 0; c < rowsPerSplit; c += 8) {
        int l = l0 + c + lr;
        size_t base = ((size_t)b * L_ + l) * D_ + h * DIM_ + ld;
        Kt[lr][ld] = Kp[base];
        Vt[lr][ld] = Vp[base];
        __syncthreads();
        #pragma unroll
        for (int r = 0; r < 8; r++) {
            float kv = Kt[r][ld];
            a0 = fmaf(kv, Vt[r][lr +  0], a0);
            a1 = fmaf(kv, Vt[r][lr +  8], a1);
            a2 = fmaf(kv, Vt[r][lr + 16], a2);
            a3 = fmaf(kv, Vt[r][lr + 24], a3);
        }
        if (tid < 32) {
            #pragma unroll
            for (int r = 0; r < 8; r++) ks += Kt[r][tid];
        }
        __syncthreads();
    }

    float* kvb = KV + (size_t)bh * DIM_ * DIM_;
    atomicAdd(&kvb[(lr +  0) * DIM_ + ld], a0);
    atomicAdd(&kvb[(lr +  8) * DIM_ + ld], a1);
    atomicAdd(&kvb[(lr + 16) * DIM_ + ld], a2);
    atomicAdd(&kvb[(lr + 24) * DIM_ + ld], a3);
    if (tid < 32) atomicAdd(&Ks[bh * DIM_ + tid], ks);
}

// ================= attention apply =================
__global__ __launch_bounds__(256)
void attn_apply(const float* __restrict__ Q, const float* __restrict__ KV,
                const float* __restrict__ Ks, float* __restrict__ Out)
{
    __shared__ float sKV[H_ * DIM_ * DIM_];
    __shared__ float sKs[H_ * DIM_];
    const int b = blockIdx.y;
    const int tid = threadIdx.x;

    for (int i = tid; i < H_ * DIM_ * DIM_; i += 256)
        sKV[i] = KV[(size_t)b * H_ * DIM_ * DIM_ + i];
    if (tid < H_ * DIM_) sKs[tid] = Ks[b * H_ * DIM_ + tid];
    __syncthreads();

    const int token = blockIdx.x * 256 + tid;
    if (token >= L_) return;
    const size_t row = (size_t)b * L_ + token;
    const float* q = Q + row * D_;
    float* o = Out + row * D_;

    for (int h = 0; h < H_; h++) {
        float qr[DIM_];
        #pragma unroll
        for (int d = 0; d < DIM_; d++) qr[d] = q[h * DIM_ + d];
        float s = 0.f;
        #pragma unroll
        for (int d = 0; d < DIM_; d++) s = fmaf(qr[d], sKs[h * DIM_ + d], s);
        float z = 1.f / (s + EPS_ATTN);
        const float* kvh = &sKV[h * DIM_ * DIM_];
        #pragma unroll 4
        for (int m = 0; m < DIM_; m++) {
            float acc = 0.f;
            #pragma unroll
            for (int d = 0; d < DIM_; d++) acc = fmaf(kvh[m * DIM_ + d], qr[d], acc);
            o[h * DIM_ + m] = acc * z;
        }
    }
}

// ================= host orchestration =================
namespace {

struct Ptrs {
    float *x0, *x1, *Q, *K, *V, *A, *Msg, *Hid, *KV, *Ks, *WT, *w1T, *w2T;
};

void run_layer(float* x, const float* src, const float* xm, const float* sm,
               const float* WqT, const float* bq, const float* WkT, const float* bk,
               const float* WvT, const float* bv, const float* WmT, const float* bm,
               const float* w1T, const float* w2T, const float* g1, const float* b1,
               const float* g2, const float* b2, const Ptrs& p)
{
    dim3 g1d(1, M_ / BM);   // (1, 600)
    dim3 g2d(2, M_ / BM);   // (2, 600)

    gemm_mma<EPI_QK><<<g1d, 256, SMEM_BYTES>>>(x,   WqT, bq, xm, nullptr, nullptr, p.Q, 256, 256);
    gemm_mma<EPI_QK><<<g1d, 256, SMEM_BYTES>>>(src, WkT, bk, sm, nullptr, nullptr, p.K, 256, 256);
    gemm_mma<EPI_V ><<<g1d, 256, SMEM_BYTES>>>(src, WvT, bv, sm, nullptr, nullptr, p.V, 256, 256);

    zero_kv<<<(KV_ELEMS + 255) / 256, 256>>>(p.KV, p.Ks);
    kv_kernel<<<dim3(B_ * H_, 20), 256>>>(p.K, p.V, p.KV, p.Ks, L_ / 20);
    attn_apply<<<dim3((L_ + 255) / 256, B_), 256>>>(p.Q, p.KV, p.Ks, p.A);

    gemm_mma<EPI_BIAS_LN><<<g1d, 256, SMEM_BYTES>>>(p.A,   WmT, bm, nullptr, g1, b1, p.Msg, 256, 256);
    gemm_mma<EPI_RELU  ><<<g2d, 256, SMEM_BYTES>>>(p.Msg, w1T, nullptr, nullptr, nullptr, nullptr, p.Hid, 512, 256);
    gemm_mma<EPI_LN_RES><<<g1d, 256, SMEM_BYTES>>>(p.Hid, w2T, nullptr, nullptr, g2, b2, x, 256, 512);
}

} // namespace

extern "C" void kernel_launch(void* const* d_in, const int* in_sizes, int n_in,
                              void* d_out, int out_size)
{
    const float* desc0 = (const float*)d_in[0];
    const float* desc1 = (const float*)d_in[1];
    const float* mask0 = (const float*)d_in[2];
    const float* mask1 = (const float*)d_in[3];
    const float* Wq = (const float*)d_in[4];
    const float* bq = (const float*)d_in[5];
    const float* Wk = (const float*)d_in[6];
    const float* bk = (const float*)d_in[7];
    const float* Wv = (const float*)d_in[8];
    const float* bv = (const float*)d_in[9];
    const float* Wm = (const float*)d_in[10];
    const float* bm = (const float*)d_in[11];
    const float* w1 = (const float*)d_in[12];
    const float* w2 = (const float*)d_in[13];
    const float* g1 = (const float*)d_in[14];
    const float* b1 = (const float*)d_in[15];
    const float* g2 = (const float*)d_in[16];
    const float* b2 = (const float*)d_in[17];

    Ptrs p;
    cudaGetSymbolAddress((void**)&p.x0,  g_x0);
    cudaGetSymbolAddress((void**)&p.x1,  g_x1);
    cudaGetSymbolAddress((void**)&p.Q,   g_Q);
    cudaGetSymbolAddress((void**)&p.K,   g_K);
    cudaGetSymbolAddress((void**)&p.V,   g_V);
    cudaGetSymbolAddress((void**)&p.A,   g_A);
    cudaGetSymbolAddress((void**)&p.Msg, g_Msg);
    cudaGetSymbolAddress((void**)&p.Hid, g_Hid);
    cudaGetSymbolAddress((void**)&p.KV,  g_KV);
    cudaGetSymbolAddress((void**)&p.Ks,  g_Ks);
    cudaGetSymbolAddress((void**)&p.WT,  g_WT);
    cudaGetSymbolAddress((void**)&p.w1T, g_w1T);
    cudaGetSymbolAddress((void**)&p.w2T, g_w2T);

    cudaFuncSetAttribute((const void*)gemm_mma<EPI_QK>,      cudaFuncAttributeMaxDynamicSharedMemorySize, SMEM_BYTES);
    cudaFuncSetAttribute((const void*)gemm_mma<EPI_V>,       cudaFuncAttributeMaxDynamicSharedMemorySize, SMEM_BYTES);
    cudaFuncSetAttribute((const void*)gemm_mma<EPI_RELU>,    cudaFuncAttributeMaxDynamicSharedMemorySize, SMEM_BYTES);
    cudaFuncSetAttribute((const void*)gemm_mma<EPI_BIAS_LN>, cudaFuncAttributeMaxDynamicSharedMemorySize, SMEM_BYTES);
    cudaFuncSetAttribute((const void*)gemm_mma<EPI_LN_RES>,  cudaFuncAttributeMaxDynamicSharedMemorySize, SMEM_BYTES);

    // ---- weight prep: transpose + tf32 rounding (once; reused by all 16 layer-calls) ----
    dim3 tb32(32, 8);
    transpose_round<<<dim3(8, 8, 1), tb32>>>(Wq, p.WT + 0 * D_ * D_, 256, 256);
    transpose_round<<<dim3(8, 8, 1), tb32>>>(Wk, p.WT + 1 * D_ * D_, 256, 256);
    transpose_round<<<dim3(8, 8, 1), tb32>>>(Wv, p.WT + 2 * D_ * D_, 256, 256);
    transpose_round<<<dim3(8, 8, 1), tb32>>>(Wm, p.WT + 3 * D_ * D_, 256, 256);
    transpose_round<<<dim3(16, 8, 8), tb32>>>(w1, p.w1T, 256, 512);   // [256,512] -> [512,256]
    transpose_round<<<dim3(8, 16, 8), tb32>>>(w2, p.w2T, 512, 256);   // [512,256] -> [256,512]

    const size_t tensorBytes = (size_t)M_ * D_ * sizeof(float);
    cudaMemcpyAsync(p.x0, desc0, tensorBytes, cudaMemcpyDeviceToDevice);
    cudaMemcpyAsync(p.x1, desc1, tensorBytes, cudaMemcpyDeviceToDevice);

    const int w1sz = D_ * 2 * D_;
    const int w2sz = 2 * D_ * D_;

    for (int li = 0; li < 8; li++) {
        const float* lw1 = p.w1T + (size_t)li * w1sz;
        const float* lw2 = p.w2T + (size_t)li * w2sz;
        const float* lg1 = g1 + li * D_;
        const float* lb1 = b1 + li * D_;
        const float* lg2 = g2 + li * D_;
        const float* lb2 = b2 + li * D_;
        const float* WqT = p.WT + 0 * D_ * D_;
        const float* WkT = p.WT + 1 * D_ * D_;
        const float* WvT = p.WT + 2 * D_ * D_;
        const float* WmT = p.WT + 3 * D_ * D_;
        if ((li & 1) == 0) {
            run_layer(p.x0, p.x0, mask0, mask0, WqT, bq, WkT, bk, WvT, bv, WmT, bm,
                      lw1, lw2, lg1, lb1, lg2, lb2, p);
            run_layer(p.x1, p.x1, mask1, mask1, WqT, bq, WkT, bk, WvT, bv, WmT, bm,
                      lw1, lw2, lg1, lb1, lg2, lb2, p);
        } else {
            run_layer(p.x0, p.x1, mask0, mask1, WqT, bq, WkT, bk, WvT, bv, WmT, bm,
                      lw1, lw2, lg1, lb1, lg2, lb2, p);
            run_layer(p.x1, p.x0, mask1, mask0, WqT, bq, WkT, bk, WvT, bv, WmT, bm,
                      lw1, lw2, lg1, lb1, lg2, lb2, p);
        }
    }

    cudaMemcpyAsync((float*)d_out,                   p.x0, tensorBytes, cudaMemcpyDeviceToDevice);
    cudaMemcpyAsync((float*)d_out + (size_t)M_ * D_, p.x1, tensorBytes, cudaMemcpyDeviceToDevice);
}

// round 5
// speedup vs baseline: 1.9463x; 1.0238x over previous
#include <cuda_runtime.h>
#include <cuda_fp16.h>
#include <math.h>
#include <stdint.h>

// ================= problem constants =================
namespace {
constexpr int B_ = 8, L_ = 4800, D_ = 256, H_ = 8, DIM_ = 32;
constexpr int M_ = B_ * L_;            // 38400 rows
constexpr float EPS_ATTN = 1e-6f, EPS_LN = 1e-5f;
constexpr int KV_ELEMS = B_ * H_ * DIM_ * DIM_;   // 65536
constexpr int KS_ELEMS = B_ * H_ * DIM_;          // 2048

// GEMM tile: CTA 64x256, BK=32, 8 warps, warp tile 64x32 (4 m-tiles x 4 n-tiles)
constexpr int BM = 64, BN = 256, BK = 32;
// dynamic smem (floats): A 2 stages x 1024 u32 (4KB), B 2 stages x 4096 u32 (16KB), params
constexpr int AS_F = 2048;                    // 8192 bytes
constexpr int BS_F = 8192;                    // 32768 bytes
constexpr int PRM_F = AS_F + BS_F;            // 10240
constexpr int SMEM_FLOATS = PRM_F + 768;
constexpr int SMEM_BYTES = SMEM_FLOATS * 4;   // 44032
}

// ================= scratch (static device globals) =================
__device__ float g_x0[M_ * D_];
__device__ float g_x1[M_ * D_];
__device__ float g_Q [M_ * D_];
__device__ float g_K [M_ * D_];
__device__ float g_V [M_ * D_];
__device__ float g_A [M_ * D_];
__device__ float g_Msg[M_ * D_];
__device__ float g_Hid[M_ * 2 * D_];
__device__ float g_KV[KV_ELEMS];
__device__ float g_Ks[KS_ELEMS];
__device__ __half g_WTh [4 * D_ * D_];        // packed frag-major fp16 weights
__device__ __half g_w1Th[8 * 2 * D_ * D_];
__device__ __half g_w2Th[8 * D_ * 2 * D_];

// ================= mma helper =================
__device__ __forceinline__ void mma_f16(float d[4], const uint32_t a[4],
                                        uint32_t b0, uint32_t b1) {
    asm volatile(
        "mma.sync.aligned.m16n8k16.row.col.f32.f16.f16.f32 "
        "{%0,%1,%2,%3}, {%4,%5,%6,%7}, {%8,%9}, {%0,%1,%2,%3};\n"
        : "+f"(d[0]), "+f"(d[1]), "+f"(d[2]), "+f"(d[3])
        : "r"(a[0]), "r"(a[1]), "r"(a[2]), "r"(a[3]), "r"(b0), "r"(b1));
}

// ================= B pack: [K,N] f32 -> fragment-major fp16 =================
// Fragment-major layout so GEMM loads B fragments with single LDS.128 and
// cp.async copies are fully linear.
__global__ void pack_B_f16(const float* __restrict__ in, __half* __restrict__ out,
                           int K, int N)
{
    int t = blockIdx.x * 256 + threadIdx.x;
    if (t >= K * N) return;
    int k = t / N, n = t % N;
    int nblk = n >> 8, nloc = n & 255;
    int wn = nloc >> 5, j = (nloc >> 3) & 3, gid = nloc & 7;
    int p = j >> 1, jh = j & 1;
    int kch = k >> 5, c16 = k & 15, kstep = (k >> 4) & 1;
    int qid = (c16 >> 1) & 3, kh = (c16 >> 3) & 1, h = c16 & 1;
    int NKCH = K >> 5;
    size_t idx = ((((((size_t)nblk * NKCH + kch) * 2 + kstep) * 8 + wn) * 2 + p) * 32
                  + qid * 8 + gid) * 8 + jh * 4 + kh * 2 + h;
    out[idx] = __float2half_rn(in[t]);
}

// ================= fp16 tensor-core GEMM, fused epilogues =================
// C[M,N] = epi(A[M,K] @ W^T) with W pre-packed frag-major fp16.
enum { EPI_QK = 1, EPI_V = 2, EPI_RELU = 3, EPI_BIAS_LN = 5, EPI_LN_RES = 6 };

template<int EPI>
__global__ __launch_bounds__(256, 2)
void gemm_f16(const float* __restrict__ A, const __half* __restrict__ Bp,
              const float* __restrict__ bias, const float* __restrict__ mask,
              const float* __restrict__ lng, const float* __restrict__ lnb,
              float* __restrict__ C, int N, int K)
{
    extern __shared__ float sm[];
    uint32_t* As = (uint32_t*)sm;                 // 2 x 1024 u32
    uint32_t* Bs = (uint32_t*)sm + AS_F;          // 2 x 4096 u32
    float* sbias = sm + PRM_F;
    float* sg    = sbias + 256;
    float* sb    = sg + 256;
    // epilogue scratch reuses A stage region after mainloop
    float* red1 = sm;                // [64][8]
    float* red2 = sm + 512;          // [64][8]
    float* smu  = sm + 1024;         // [64]
    float* srs  = sm + 1088;         // [64]

    const int tid = threadIdx.x;
    const int wn = tid >> 5, lane = tid & 31;
    const int gid = lane >> 2, qid = lane & 3;
    const int rowBase = blockIdx.y * BM;
    const int colBase = blockIdx.x * BN;
    const int NKCH = K >> 5;

    if (EPI == EPI_QK || EPI == EPI_V || EPI == EPI_BIAS_LN)
        sbias[tid] = bias[colBase + tid];
    if (EPI == EPI_BIAS_LN || EPI == EPI_LN_RES) { sg[tid] = lng[tid]; sb[tid] = lnb[tid]; }

    const uint32_t sm_b = (uint32_t)__cvta_generic_to_shared(sm);

    // A staging: thread handles row r=tid&63, cols cseg*8..+8
    const int ar = tid & 63, cseg = tid >> 6;
    const int a_mi = ar >> 4, a_slot = (ar >> 3) & 1, a_gid = ar & 7;
    const int a_kstep = cseg >> 1, a_kh = cseg & 1;
    const float* Aptr = A + (size_t)(rowBase + ar) * K + cseg * 8;
    // precomputed STS base (u32 units within stage)
    const int a_sts = (a_kstep * 4 + a_mi) * 128 + a_gid * 4 + a_kh * 2 + a_slot;
    float4 abuf[2];

    #define LDG_A(c)                                                           \
        do { abuf[0] = *(const float4*)(Aptr + (size_t)(c) * 32);              \
             abuf[1] = *(const float4*)(Aptr + (size_t)(c) * 32 + 4);          \
        } while (0)

    #define STS_A(s)                                                           \
        do { uint32_t* _d = As + (s) * 1024;                                   \
            const float* _f = (const float*)abuf;                              \
            _Pragma("unroll")                                                  \
            for (int _q = 0; _q < 4; _q++) {                                   \
                __half2 _h = __float22half2_rn(make_float2(_f[2*_q], _f[2*_q+1])); \
                _d[a_sts + _q * 32] = *(const uint32_t*)&_h;                    \
            }                                                                   \
        } while (0)

    #define LDG_B(c, s)                                                        \
        do { uint32_t _dst = sm_b + AS_F * 4 + (s) * 16384 + tid * 16;         \
            const __half* _src = Bp + (((size_t)blockIdx.x * NKCH + (c)) << 13) + tid * 8; \
            _Pragma("unroll")                                                  \
            for (int _it = 0; _it < 4; _it++)                                  \
                asm volatile("cp.async.cg.shared.global [%0], [%1], 16;"       \
                             :: "r"(_dst + _it * 4096), "l"(_src + _it * 2048)); \
            asm volatile("cp.async.commit_group;");                            \
        } while (0)

    float acc[4][4][4];
    #pragma unroll
    for (int mi = 0; mi < 4; mi++)
        #pragma unroll
        for (int j = 0; j < 4; j++)
            #pragma unroll
            for (int q = 0; q < 4; q++) acc[mi][j][q] = 0.f;

    LDG_A(0);
    STS_A(0);
    LDG_B(0, 0);

    const int fragoff = (qid * 8 + gid) * 4;
    for (int k = 0; k < NKCH; k++) {
        const int s = k & 1;
        if (k + 1 < NKCH) LDG_A(k + 1);
        asm volatile("cp.async.wait_group 0;" ::: "memory");
        __syncthreads();
        if (k + 1 < NKCH) { STS_A(s ^ 1); LDG_B(k + 1, s ^ 1); }

        const uint32_t* as = As + s * 1024;
        const uint32_t* bs = Bs + s * 4096;
        #pragma unroll
        for (int kst = 0; kst < 2; kst++) {
            uint4 af[4], bf[2];
            #pragma unroll
            for (int mi = 0; mi < 4; mi++)
                af[mi] = *(const uint4*)(as + (kst * 4 + mi) * 128 + fragoff);
            #pragma unroll
            for (int p = 0; p < 2; p++)
                bf[p] = *(const uint4*)(bs + ((kst * 8 + wn) * 2 + p) * 128 + fragoff);
            #pragma unroll
            for (int mi = 0; mi < 4; mi++) {
                const uint32_t a4[4] = {af[mi].x, af[mi].y, af[mi].z, af[mi].w};
                mma_f16(acc[mi][0], a4, bf[0].x, bf[0].y);
                mma_f16(acc[mi][1], a4, bf[0].z, bf[0].w);
                mma_f16(acc[mi][2], a4, bf[1].x, bf[1].y);
                mma_f16(acc[mi][3], a4, bf[1].z, bf[1].w);
            }
        }
    }
    __syncthreads();   // done with staging smem

    // ================= epilogue =================
    // element (mi,j,q): row = rowBase + mi*16 + (q>>1)*8 + gid
    //                   col = colBase + wn*32 + j*8 + qid*2 + (q&1)
    if (EPI == EPI_QK || EPI == EPI_V || EPI == EPI_BIAS_LN) {
        #pragma unroll
        for (int mi = 0; mi < 4; mi++)
            #pragma unroll
            for (int j = 0; j < 4; j++) {
                const int c = wn * 32 + j * 8 + qid * 2;
                acc[mi][j][0] += sbias[c];   acc[mi][j][1] += sbias[c + 1];
                acc[mi][j][2] += sbias[c];   acc[mi][j][3] += sbias[c + 1];
            }
    }
    if (EPI == EPI_QK || EPI == EPI_V) {
        float mk[4][2];
        #pragma unroll
        for (int mi = 0; mi < 4; mi++)
            #pragma unroll
            for (int r = 0; r < 2; r++)
                mk[mi][r] = mask[rowBase + mi * 16 + r * 8 + gid];
        #pragma unroll
        for (int mi = 0; mi < 4; mi++)
            #pragma unroll
            for (int j = 0; j < 4; j++)
                #pragma unroll
                for (int q = 0; q < 4; q++) {
                    float t = acc[mi][j][q];
                    if (EPI == EPI_QK) t = (t > 0.f) ? (t + 1.f) : expf(t);
                    acc[mi][j][q] = t * mk[mi][q >> 1];
                }
    }
    if (EPI == EPI_RELU) {
        #pragma unroll
        for (int mi = 0; mi < 4; mi++)
            #pragma unroll
            for (int j = 0; j < 4; j++)
                #pragma unroll
                for (int q = 0; q < 4; q++)
                    acc[mi][j][q] = acc[mi][j][q] > 0.f ? acc[mi][j][q] : 0.f;
    }

    if (EPI == EPI_BIAS_LN || EPI == EPI_LN_RES) {
        float s1[4][2], s2[4][2];
        #pragma unroll
        for (int mi = 0; mi < 4; mi++)
            #pragma unroll
            for (int r = 0; r < 2; r++) { s1[mi][r] = 0.f; s2[mi][r] = 0.f; }
        #pragma unroll
        for (int mi = 0; mi < 4; mi++)
            #pragma unroll
            for (int j = 0; j < 4; j++)
                #pragma unroll
                for (int q = 0; q < 4; q++) {
                    float v = acc[mi][j][q];
                    s1[mi][q >> 1] += v;
                    s2[mi][q >> 1] = fmaf(v, v, s2[mi][q >> 1]);
                }
        #pragma unroll
        for (int o = 1; o <= 2; o <<= 1)
            #pragma unroll
            for (int mi = 0; mi < 4; mi++)
                #pragma unroll
                for (int r = 0; r < 2; r++) {
                    s1[mi][r] += __shfl_xor_sync(0xffffffffu, s1[mi][r], o);
                    s2[mi][r] += __shfl_xor_sync(0xffffffffu, s2[mi][r], o);
                }
        if (qid == 0) {
            #pragma unroll
            for (int mi = 0; mi < 4; mi++)
                #pragma unroll
                for (int r = 0; r < 2; r++) {
                    int rl = mi * 16 + r * 8 + gid;
                    red1[rl * 8 + wn] = s1[mi][r];
                    red2[rl * 8 + wn] = s2[mi][r];
                }
        }
        __syncthreads();
        if (tid < 64) {
            float a = 0.f, b2 = 0.f;
            #pragma unroll
            for (int w = 0; w < 8; w++) { a += red1[tid * 8 + w]; b2 += red2[tid * 8 + w]; }
            float mu = a * (1.f / 256.f);
            float var = b2 * (1.f / 256.f) - mu * mu;
            smu[tid] = mu;
            srs[tid] = rsqrtf(var + EPS_LN);
        }
        __syncthreads();
        #pragma unroll
        for (int mi = 0; mi < 4; mi++)
            #pragma unroll
            for (int j = 0; j < 4; j++)
                #pragma unroll
                for (int q = 0; q < 4; q++) {
                    int rl = mi * 16 + (q >> 1) * 8 + gid;
                    int c  = wn * 32 + j * 8 + qid * 2 + (q & 1);
                    acc[mi][j][q] = (acc[mi][j][q] - smu[rl]) * srs[rl] * sg[c] + sb[c];
                }
    }

    // store
    #pragma unroll
    for (int mi = 0; mi < 4; mi++) {
        #pragma unroll
        for (int j = 0; j < 4; j++) {
            const int c  = colBase + wn * 32 + j * 8 + qid * 2;
            const int r0 = rowBase + mi * 16 + gid;
            const int r1 = r0 + 8;
            float2 v0 = make_float2(acc[mi][j][0], acc[mi][j][1]);
            float2 v1 = make_float2(acc[mi][j][2], acc[mi][j][3]);
            if (EPI == EPI_LN_RES) {
                float2 x0 = *(const float2*)&C[(size_t)r0 * N + c];
                float2 x1 = *(const float2*)&C[(size_t)r1 * N + c];
                v0.x += x0.x; v0.y += x0.y;
                v1.x += x1.x; v1.y += x1.y;
            }
            *(float2*)&C[(size_t)r0 * N + c] = v0;
            *(float2*)&C[(size_t)r1 * N + c] = v1;
        }
    }
    #undef LDG_A
    #undef STS_A
    #undef LDG_B
}

// ================= zero KV / Ksum =================
__global__ void zero_kv(float* __restrict__ kv, float* __restrict__ ks)
{
    int i = blockIdx.x * 256 + threadIdx.x;
    if (i < KV_ELEMS) kv[i] = 0.f;
    if (i < KS_ELEMS) ks[i] = 0.f;
}

// ================= KV reduction =================
__global__ __launch_bounds__(256)
void kv_kernel(const float* __restrict__ Kp, const float* __restrict__ Vp,
               float* __restrict__ KV, float* __restrict__ Ks, int rowsPerSplit)
{
    const int bh = blockIdx.x;
    const int b = bh >> 3, h = bh & 7;
    const int l0 = blockIdx.y * rowsPerSplit;
    const int tid = threadIdx.x;
    const int lr = tid >> 5;
    const int ld = tid & 31;

    __shared__ float Kt[8][32];
    __shared__ float Vt[8][32];

    float a0 = 0.f, a1 = 0.f, a2 = 0.f, a3 = 0.f, ks = 0.f;

    for (int c = 0; c < rowsPerSplit; c += 8) {
        int l = l0 + c + lr;
        size_t base = ((size_t)b * L_ + l) * D_ + h * DIM_ + ld;
        Kt[lr][ld] = Kp[base];
        Vt[lr][ld] = Vp[base];
        __syncthreads();
        #pragma unroll
        for (int r = 0; r < 8; r++) {
            float kv = Kt[r][ld];
            a0 = fmaf(kv, Vt[r][lr +  0], a0);
            a1 = fmaf(kv, Vt[r][lr +  8], a1);
            a2 = fmaf(kv, Vt[r][lr + 16], a2);
            a3 = fmaf(kv, Vt[r][lr + 24], a3);
        }
        if (tid < 32) {
            #pragma unroll
            for (int r = 0; r < 8; r++) ks += Kt[r][tid];
        }
        __syncthreads();
    }

    float* kvb = KV + (size_t)bh * DIM_ * DIM_;
    atomicAdd(&kvb[(lr +  0) * DIM_ + ld], a0);
    atomicAdd(&kvb[(lr +  8) * DIM_ + ld], a1);
    atomicAdd(&kvb[(lr + 16) * DIM_ + ld], a2);
    atomicAdd(&kvb[(lr + 24) * DIM_ + ld], a3);
    if (tid < 32) atomicAdd(&Ks[bh * DIM_ + tid], ks);
}

// ================= attention apply =================
__global__ __launch_bounds__(256)
void attn_apply(const float* __restrict__ Q, const float* __restrict__ KV,
                const float* __restrict__ Ks, float* __restrict__ Out)
{
    __shared__ float sKV[H_ * DIM_ * DIM_];
    __shared__ float sKs[H_ * DIM_];
    const int b = blockIdx.y;
    const int tid = threadIdx.x;

    for (int i = tid; i < H_ * DIM_ * DIM_; i += 256)
        sKV[i] = KV[(size_t)b * H_ * DIM_ * DIM_ + i];
    if (tid < H_ * DIM_) sKs[tid] = Ks[b * H_ * DIM_ + tid];
    __syncthreads();

    const int token = blockIdx.x * 256 + tid;
    if (token >= L_) return;
    const size_t row = (size_t)b * L_ + token;
    const float* q = Q + row * D_;
    float* o = Out + row * D_;

    for (int h = 0; h < H_; h++) {
        float qr[DIM_];
        #pragma unroll
        for (int d = 0; d < DIM_; d++) qr[d] = q[h * DIM_ + d];
        float s = 0.f;
        #pragma unroll
        for (int d = 0; d < DIM_; d++) s = fmaf(qr[d], sKs[h * DIM_ + d], s);
        float z = 1.f / (s + EPS_ATTN);
        const float* kvh = &sKV[h * DIM_ * DIM_];
        #pragma unroll 4
        for (int m = 0; m < DIM_; m++) {
            float acc = 0.f;
            #pragma unroll
            for (int d = 0; d < DIM_; d++) acc = fmaf(kvh[m * DIM_ + d], qr[d], acc);
            o[h * DIM_ + m] = acc * z;
        }
    }
}

// ================= host orchestration =================
namespace {

struct Ptrs {
    float *x0, *x1, *Q, *K, *V, *A, *Msg, *Hid, *KV, *Ks;
    __half *WTh, *w1Th, *w2Th;
};

void run_layer(float* x, const float* src, const float* xm, const float* sm,
               const __half* WqP, const float* bq, const __half* WkP, const float* bk,
               const __half* WvP, const float* bv, const __half* WmP, const float* bm,
               const __half* w1P, const __half* w2P, const float* g1, const float* b1,
               const float* g2, const float* b2, const Ptrs& p)
{
    dim3 g1d(1, M_ / BM);   // (1, 600)
    dim3 g2d(2, M_ / BM);   // (2, 600)

    gemm_f16<EPI_QK><<<g1d, 256, SMEM_BYTES>>>(x,   WqP, bq, xm, nullptr, nullptr, p.Q, 256, 256);
    gemm_f16<EPI_QK><<<g1d, 256, SMEM_BYTES>>>(src, WkP, bk, sm, nullptr, nullptr, p.K, 256, 256);
    gemm_f16<EPI_V ><<<g1d, 256, SMEM_BYTES>>>(src, WvP, bv, sm, nullptr, nullptr, p.V, 256, 256);

    zero_kv<<<(KV_ELEMS + 255) / 256, 256>>>(p.KV, p.Ks);
    kv_kernel<<<dim3(B_ * H_, 20), 256>>>(p.K, p.V, p.KV, p.Ks, L_ / 20);
    attn_apply<<<dim3((L_ + 255) / 256, B_), 256>>>(p.Q, p.KV, p.Ks, p.A);

    gemm_f16<EPI_BIAS_LN><<<g1d, 256, SMEM_BYTES>>>(p.A,   WmP, bm, nullptr, g1, b1, p.Msg, 256, 256);
    gemm_f16<EPI_RELU  ><<<g2d, 256, SMEM_BYTES>>>(p.Msg, w1P, nullptr, nullptr, nullptr, nullptr, p.Hid, 512, 256);
    gemm_f16<EPI_LN_RES><<<g1d, 256, SMEM_BYTES>>>(p.Hid, w2P, nullptr, nullptr, g2, b2, x, 256, 512);
}

} // namespace

extern "C" void kernel_launch(void* const* d_in, const int* in_sizes, int n_in,
                              void* d_out, int out_size)
{
    const float* desc0 = (const float*)d_in[0];
    const float* desc1 = (const float*)d_in[1];
    const float* mask0 = (const float*)d_in[2];
    const float* mask1 = (const float*)d_in[3];
    const float* Wq = (const float*)d_in[4];
    const float* bq = (const float*)d_in[5];
    const float* Wk = (const float*)d_in[6];
    const float* bk = (const float*)d_in[7];
    const float* Wv = (const float*)d_in[8];
    const float* bv = (const float*)d_in[9];
    const float* Wm = (const float*)d_in[10];
    const float* bm = (const float*)d_in[11];
    const float* w1 = (const float*)d_in[12];
    const float* w2 = (const float*)d_in[13];
    const float* g1 = (const float*)d_in[14];
    const float* b1 = (const float*)d_in[15];
    const float* g2 = (const float*)d_in[16];
    const float* b2 = (const float*)d_in[17];

    Ptrs p;
    cudaGetSymbolAddress((void**)&p.x0,  g_x0);
    cudaGetSymbolAddress((void**)&p.x1,  g_x1);
    cudaGetSymbolAddress((void**)&p.Q,   g_Q);
    cudaGetSymbolAddress((void**)&p.K,   g_K);
    cudaGetSymbolAddress((void**)&p.V,   g_V);
    cudaGetSymbolAddress((void**)&p.A,   g_A);
    cudaGetSymbolAddress((void**)&p.Msg, g_Msg);
    cudaGetSymbolAddress((void**)&p.Hid, g_Hid);
    cudaGetSymbolAddress((void**)&p.KV,  g_KV);
    cudaGetSymbolAddress((void**)&p.Ks,  g_Ks);
    cudaGetSymbolAddress((void**)&p.WTh,  g_WTh);
    cudaGetSymbolAddress((void**)&p.w1Th, g_w1Th);
    cudaGetSymbolAddress((void**)&p.w2Th, g_w2Th);

    cudaFuncSetAttribute((const void*)gemm_f16<EPI_QK>,      cudaFuncAttributeMaxDynamicSharedMemorySize, SMEM_BYTES);
    cudaFuncSetAttribute((const void*)gemm_f16<EPI_V>,       cudaFuncAttributeMaxDynamicSharedMemorySize, SMEM_BYTES);
    cudaFuncSetAttribute((const void*)gemm_f16<EPI_RELU>,    cudaFuncAttributeMaxDynamicSharedMemorySize, SMEM_BYTES);
    cudaFuncSetAttribute((const void*)gemm_f16<EPI_BIAS_LN>, cudaFuncAttributeMaxDynamicSharedMemorySize, SMEM_BYTES);
    cudaFuncSetAttribute((const void*)gemm_f16<EPI_LN_RES>,  cudaFuncAttributeMaxDynamicSharedMemorySize, SMEM_BYTES);

    // ---- one-time weight packing to fragment-major fp16 ----
    const int w1sz = D_ * 2 * D_;   // 131072
    const int w2sz = 2 * D_ * D_;
    pack_B_f16<<<(D_ * D_ + 255) / 256, 256>>>(Wq, p.WTh + 0 * D_ * D_, 256, 256);
    pack_B_f16<<<(D_ * D_ + 255) / 256, 256>>>(Wk, p.WTh + 1 * D_ * D_, 256, 256);
    pack_B_f16<<<(D_ * D_ + 255) / 256, 256>>>(Wv, p.WTh + 2 * D_ * D_, 256, 256);
    pack_B_f16<<<(D_ * D_ + 255) / 256, 256>>>(Wm, p.WTh + 3 * D_ * D_, 256, 256);
    for (int li = 0; li < 8; li++) {
        pack_B_f16<<<(w1sz + 255) / 256, 256>>>(w1 + (size_t)li * w1sz, p.w1Th + (size_t)li * w1sz, 256, 512);
        pack_B_f16<<<(w2sz + 255) / 256, 256>>>(w2 + (size_t)li * w2sz, p.w2Th + (size_t)li * w2sz, 512, 256);
    }

    const size_t tensorBytes = (size_t)M_ * D_ * sizeof(float);
    cudaMemcpyAsync(p.x0, desc0, tensorBytes, cudaMemcpyDeviceToDevice);
    cudaMemcpyAsync(p.x1, desc1, tensorBytes, cudaMemcpyDeviceToDevice);

    for (int li = 0; li < 8; li++) {
        const __half* lw1 = p.w1Th + (size_t)li * w1sz;
        const __half* lw2 = p.w2Th + (size_t)li * w2sz;
        const float* lg1 = g1 + li * D_;
        const float* lb1 = b1 + li * D_;
        const float* lg2 = g2 + li * D_;
        const float* lb2 = b2 + li * D_;
        const __half* WqP = p.WTh + 0 * D_ * D_;
        const __half* WkP = p.WTh + 1 * D_ * D_;
        const __half* WvP = p.WTh + 2 * D_ * D_;
        const __half* WmP = p.WTh + 3 * D_ * D_;
        if ((li & 1) == 0) {
            run_layer(p.x0, p.x0, mask0, mask0, WqP, bq, WkP, bk, WvP, bv, WmP, bm,
                      lw1, lw2, lg1, lb1, lg2, lb2, p);
            run_layer(p.x1, p.x1, mask1, mask1, WqP, bq, WkP, bk, WvP, bv, WmP, bm,
                      lw1, lw2, lg1, lb1, lg2, lb2, p);
        } else {
            run_layer(p.x0, p.x1, mask0, mask1, WqP, bq, WkP, bk, WvP, bv, WmP, bm,
                      lw1, lw2, lg1, lb1, lg2, lb2, p);
            run_layer(p.x1, p.x0, mask1, mask0, WqP, bq, WkP, bk, WvP, bv, WmP, bm,
                      lw1, lw2, lg1, lb1, lg2, lb2, p);
        }
    }

    cudaMemcpyAsync((float*)d_out,                   p.x0, tensorBytes, cudaMemcpyDeviceToDevice);
    cudaMemcpyAsync((float*)d_out + (size_t)M_ * D_, p.x1, tensorBytes, cudaMemcpyDeviceToDevice);
}